// round 6
// baseline (speedup 1.0000x reference)
#include <cuda_runtime.h>
#include <cuda_bf16.h>
#include <cstdint>

// Problem constants
#define Bb   16
#define Cc   1024
#define Nn   32
#define Hh   8
#define Dd   128
#define NP   (Bb*Cc)          // 16384 (b,c) pairs
#define QSCALE 0.25f          // Dh^-0.5 = 16^-0.5

// Scratch (device globals — no runtime allocation allowed)
__device__ float g_query[(size_t)NP * Dd];           // 8 MB
__device__ float g_wsum[(size_t)NP * Hh * Dd];       // 64 MB
__device__ float g_asum[(size_t)NP * Hh];            // 512 KB

// ---- packed fp32x2 helpers (Blackwell FFMA2) -------------------------------
typedef unsigned long long ull;
__device__ __forceinline__ ull fma2(ull a, ull b, ull c) {
    ull d; asm("fma.rn.f32x2 %0, %1, %2, %3;" : "=l"(d) : "l"(a), "l"(b), "l"(c));
    return d;
}
__device__ __forceinline__ ull pk2(float lo, float hi) {
    ull r; asm("mov.b64 %0, {%1, %2};" : "=l"(r) : "f"(lo), "f"(hi)); return r;
}
__device__ __forceinline__ float2 upk2(ull v) {
    float2 r; asm("mov.b64 {%0, %1}, %2;" : "=f"(r.x), "=f"(r.y) : "l"(v)); return r;
}
#define U64(d) __double_as_longlong(d)

// ---------------------------------------------------------------------------
// K1: query[p,d] = atom_query[p,:] @ Wq + bq      (32 pairs per block)
// ---------------------------------------------------------------------------
__global__ __launch_bounds__(256) void k_query(const float* __restrict__ aq,
                                               const float* __restrict__ Wq,
                                               const float* __restrict__ bq)
{
    extern __shared__ float sm[];
    float* Wq_s = sm;                  // 128*132
    float* aq_s = Wq_s + 128 * 132;    // 32*132
    float* bq_s = aq_s + 32 * 132;     // 128
    const int t = threadIdx.x;

    #pragma unroll
    for (int j = 0; j < 16; j++) {
        int i4 = t + j * 256;
        int f = i4 >> 5, d4 = i4 & 31;
        float4 v = ((const float4*)Wq)[i4];
        *(float4*)&Wq_s[f * 132 + d4 * 4] = v;
    }
    if (t < 128) bq_s[t] = bq[t];

    const int p0 = blockIdx.x * 32;
    #pragma unroll
    for (int j = 0; j < 4; j++) {
        int i4 = t + j * 256;
        int pl = i4 >> 5, e4 = i4 & 31;
        float4 v = ((const float4*)(aq + (size_t)p0 * Dd))[i4];
        *(float4*)&aq_s[pl * 132 + e4 * 4] = v;
    }
    __syncthreads();

    const int w = t >> 5, lane = t & 31;
    const int pl0 = w * 4, d0 = lane * 4;
    ull acc[4][2];
    #pragma unroll
    for (int k = 0; k < 4; k++) { acc[k][0] = 0ULL; acc[k][1] = 0ULL; }
    #pragma unroll 4
    for (int f = 0; f < 128; f++) {
        double2 wv = *(double2*)&Wq_s[f * 132 + d0];     // LDS.128
        #pragma unroll
        for (int k = 0; k < 4; k++) {
            float a = aq_s[(pl0 + k) * 132 + f];         // broadcast
            ull a2 = pk2(a, a);
            acc[k][0] = fma2(a2, U64(wv.x), acc[k][0]);
            acc[k][1] = fma2(a2, U64(wv.y), acc[k][1]);
        }
    }
    float4 b4 = *(float4*)&bq_s[d0];
    #pragma unroll
    for (int k = 0; k < 4; k++) {
        float2 lo = upk2(acc[k][0]), hi = upk2(acc[k][1]);
        float4 r = { lo.x + b4.x, lo.y + b4.y, hi.x + b4.z, hi.y + b4.w };
        *(float4*)&g_query[(size_t)(p0 + pl0 + k) * Dd + d0] = r;
    }
}

// ---------------------------------------------------------------------------
// K2: per 8-pair batch. qk staged in 4 quarter-stages of Wk; per pair:
//     prefetched gated an -> full-dot energy per (n,h) thread -> softmax -> wsum
// smem = 14272 floats = 57088 B  -> 4 CTAs/SM (32 warps)
// ---------------------------------------------------------------------------
__global__ __launch_bounds__(256, 4) void k_main(const float* __restrict__ anb,
                                                 const float* __restrict__ ldist,
                                                 const float* __restrict__ maskp,
                                                 const float* __restrict__ Wk,
                                                 const float* __restrict__ bk,
                                                 const float* __restrict__ Wf,
                                                 const float* __restrict__ bf,
                                                 float* __restrict__ attn_out)
{
    extern __shared__ float sm[];
    // persistent
    float* qk_s = sm;                    // 8p*8h rows * 132 = 8448
    float* eb_s = sm + 8448;             // 64
    float* U    = sm + 8512;             // union (5760 floats)
    // phase 1 view
    float* Wk_s    = U;                  // 128e * 36 = 4608 (quarter of out-dim)
    float* query_s = U + 4608;           // 8*128 = 1024
    float* bk_s    = U + 5632;           // 128
    // phase 2 view
    float* an_s     = U;                 // 32*132 = 4224
    float* energy_s = U + 4224;          // 8*36 = 288  [h*36 + n]
    float* attn_s   = U + 4512;          // 32*12 = 384 [n*12 + h]

    const int t = threadIdx.x;
    const int p0 = blockIdx.x * 8;

    // per-thread constant gate params (thread only ever touches e = 4*(t&31)..+3)
    const float4 Wf4 = ((const float4*)Wf)[t & 31];
    const float4 bf4 = ((const float4*)bf)[t & 31];

    if (t < 128) bk_s[t] = bk[t];
    ((float4*)query_s)[t] = ((const float4*)(g_query + (size_t)p0 * Dd))[t];

    // ---- qk: 4 stages, each covers 2 heads (32 out-dims)
    const int e_col = t & 127, hl = t >> 7;
    #pragma unroll
    for (int s = 0; s < 4; s++) {
        __syncthreads();   // covers query/bk stores (s=0) and Wk_s reuse (s>0)
        #pragma unroll
        for (int j = 0; j < 4; j++) {
            int idx = t + j * 256;                  // 0..1023
            int e = idx >> 3, q = idx & 7;          // 8 float4 per e-row
            float4 v = ((const float4*)Wk)[e * 32 + s * 8 + q];
            *(float4*)&Wk_s[e * 36 + q * 4] = v;
        }
        __syncthreads();
        const int h = s * 2 + hl;
        ull wk2[8];
        #pragma unroll
        for (int i = 0; i < 4; i++) {
            double2 w2 = *(double2*)&Wk_s[e_col * 36 + hl * 16 + i * 4];
            wk2[i * 2 + 0] = U64(w2.x);
            wk2[i * 2 + 1] = U64(w2.y);
        }
        #pragma unroll
        for (int p = 0; p < 8; p++) {
            ull acc2 = 0ULL;
            #pragma unroll
            for (int i = 0; i < 4; i++) {
                double2 q2 = *(double2*)&query_s[p * 128 + h * 16 + i * 4]; // bcast
                acc2 = fma2(wk2[i * 2 + 0], U64(q2.x), acc2);
                acc2 = fma2(wk2[i * 2 + 1], U64(q2.y), acc2);
            }
            float2 a = upk2(acc2);
            qk_s[(p * 8 + h) * 132 + e_col] = (a.x + a.y) * QSCALE;
        }
    }
    __syncthreads();
    // energy bias eb[p,h] = scaled q . bk  (query_s/bk_s still valid)
    if (t < 64) {
        int p = t >> 3, h = t & 7;
        float acc = 0.f;
        #pragma unroll
        for (int dd = 0; dd < 16; dd++)
            acc += query_s[p * 128 + h * 16 + dd] * bk_s[h * 16 + dd];
        eb_s[t] = acc * QSCALE;
    }
    __syncthreads();

    const int w = t >> 5, lane = t & 31;

    // prefetch for pair 0
    float4 pf[4]; float pm;
    {
        const float4* anp = (const float4*)(anb + (size_t)p0 * (Nn * Dd));
        #pragma unroll
        for (int j = 0; j < 4; j++) pf[j] = anp[t + j * 256];
        pm = __ldg(&maskp[(size_t)p0 * Nn + lane]);
    }

    for (int pl = 0; pl < 8; pl++) {
        const size_t p = (size_t)(p0 + pl);
        const float pm_cur = pm;

        // ---- A: gated an: an[n,e] = anb * swish(dist*Wf+bf)
        #pragma unroll
        for (int j = 0; j < 4; j++) {
            int n = (t + j * 256) >> 5;
            float4 v = pf[j];
            float dval = __ldg(&ldist[p * Nn + n]);
            float x0 = fmaf(dval, Wf4.x, bf4.x);
            float x1 = fmaf(dval, Wf4.y, bf4.y);
            float x2 = fmaf(dval, Wf4.z, bf4.z);
            float x3 = fmaf(dval, Wf4.w, bf4.w);
            float4 g;
            g.x = v.x * __fdividef(x0, 1.f + __expf(-x0));
            g.y = v.y * __fdividef(x1, 1.f + __expf(-x1));
            g.z = v.z * __fdividef(x2, 1.f + __expf(-x2));
            g.w = v.w * __fdividef(x3, 1.f + __expf(-x3));
            *(float4*)&an_s[n * 132 + (t & 31) * 4] = g;
        }
        __syncthreads();

        // prefetch next pair while B/C/D run
        if (pl < 7) {
            const float4* anp = (const float4*)(anb + (p + 1) * (Nn * Dd));
            #pragma unroll
            for (int j = 0; j < 4; j++) pf[j] = anp[t + j * 256];
            pm = __ldg(&maskp[(p + 1) * Nn + lane]);
        }

        // ---- B: energy[n,h] full dot; thread = (n = t>>3, h = t&7)
        {
            const int n = t >> 3, h = t & 7;
            const float* anr = &an_s[n * 132];
            const float* qkr = &qk_s[(pl * 8 + h) * 132];
            ull acc0 = 0ULL, acc1 = 0ULL;
            #pragma unroll 8
            for (int i = 0; i < 32; i++) {
                double2 a = *(const double2*)&anr[i * 4];   // 4n rows, 8-way bcast
                double2 q = *(const double2*)&qkr[i * 4];   // 8h rows, 4-way bcast
                acc0 = fma2(U64(a.x), U64(q.x), acc0);
                acc1 = fma2(U64(a.y), U64(q.y), acc1);
            }
            float2 r0 = upk2(acc0), r1 = upk2(acc1);
            energy_s[h * 36 + n] = r0.x + r0.y + r1.x + r1.y + eb_s[pl * 8 + h];
        }
        __syncthreads();

        // ---- C: softmax over n (no max pass): warp w = head, lane = n
        {
            const int h = w, n = lane;
            float en = energy_s[h * 36 + n];
            en += (1.f - pm_cur) * (-1e9f);
            float ex = __expf(en);
            float exm = ex * pm_cur;
            float s = ex, smm = exm;
            #pragma unroll
            for (int o = 16; o > 0; o >>= 1) {
                s   += __shfl_xor_sync(0xffffffffu, s, o);
                smm += __shfl_xor_sync(0xffffffffu, smm, o);
            }
            float rinv = __fdividef(1.f, s);
            float at = ex * rinv;
            if (attn_out) {
                int b = (int)(p >> 10), c = (int)(p & 1023);
                attn_out[((size_t)(b * Hh + h) * Cc + c) * Nn + n] = at;
            }
            attn_s[n * 12 + h] = at * pm_cur;
            if (n == 0) g_asum[p * Hh + h] = smm * rinv;
        }
        __syncthreads();

        // ---- D: wsum[h,e] = sum_n attnm[h,n]*an[n,e]; thread = (e, h-half)
        {
            const int e = t & 127, hh = t >> 7;
            ull acc01 = 0ULL, acc23 = 0ULL;
            #pragma unroll 8
            for (int n = 0; n < 32; n++) {
                float av = an_s[n * 132 + e];                      // conflict-free
                ull av2 = pk2(av, av);
                double2 at2 = *(double2*)&attn_s[n * 12 + hh * 4]; // bcast LDS.128
                acc01 = fma2(av2, U64(at2.x), acc01);
                acc23 = fma2(av2, U64(at2.y), acc23);
            }
            float2 a01 = upk2(acc01), a23 = upk2(acc23);
            float* wout = &g_wsum[(p * Hh + hh * 4) * Dd + e];
            wout[0] = a01.x; wout[128] = a01.y; wout[256] = a23.x; wout[384] = a23.y;
        }
        __syncthreads();
    }
}

// ---------------------------------------------------------------------------
// K3: context[p, h*16+dd] = wsum[p,h,:] @ Wv[:, h*16+dd] + asum*bv + query
// 8 pairs per block. smem = 25024 floats = 100096 B -> 2 CTAs/SM
// ---------------------------------------------------------------------------
__global__ __launch_bounds__(256, 2) void k_ctx(const float* __restrict__ Wv,
                                                const float* __restrict__ bv,
                                                float* __restrict__ ctx_out)
{
    extern __shared__ float sm[];
    float* Wv_s   = sm;                  // 128*128 = 16384
    float* ws_s   = sm + 16384;          // 64 rows (8p*8h) * 132 = 8448
    float* asum_s = sm + 24832;          // 64
    float* bv_s   = sm + 24896;          // 128

    const int t = threadIdx.x;
    const int p0 = blockIdx.x * 8;

    #pragma unroll
    for (int j = 0; j < 16; j++) {
        int i4 = t + j * 256;
        ((float4*)Wv_s)[i4] = ((const float4*)Wv)[i4];
    }
    #pragma unroll
    for (int j = 0; j < 8; j++) {
        int i4 = t + j * 256;
        int row = i4 >> 5, e4 = i4 & 31;
        float4 v = ((const float4*)(g_wsum + (size_t)p0 * Hh * Dd))[i4];
        *(float4*)&ws_s[row * 132 + e4 * 4] = v;
    }
    if (t < 64)  asum_s[t] = g_asum[(size_t)p0 * Hh + t];
    if (t < 128) bv_s[t] = bv[t];
    __syncthreads();

    const int pl = t >> 5, lane = t & 31;
    const int h = lane >> 2, dd0 = (lane & 3) * 4;
    const float* wr  = &ws_s[(pl * 8 + h) * 132];
    const float* wvp = &Wv_s[h * 16 + dd0];
    ull acc01 = 0ULL, acc23 = 0ULL;
    #pragma unroll 8
    for (int e = 0; e < 128; e++) {
        float s = wr[e];                           // 8 banks, 4-way bcast
        ull s2 = pk2(s, s);
        double2 wv = *(const double2*)&wvp[e * 128];
        acc01 = fma2(s2, U64(wv.x), acc01);
        acc23 = fma2(s2, U64(wv.y), acc23);
    }
    float as = asum_s[pl * 8 + h];
    float4 b4 = *(const float4*)&bv_s[h * 16 + dd0];
    float4 q4 = *(const float4*)&g_query[(size_t)(p0 + pl) * Dd + h * 16 + dd0];
    float2 a01 = upk2(acc01), a23 = upk2(acc23);
    float4 r;
    r.x = a01.x + as * b4.x + q4.x;
    r.y = a01.y + as * b4.y + q4.y;
    r.z = a23.x + as * b4.z + q4.z;
    r.w = a23.y + as * b4.w + q4.w;
    *(float4*)&ctx_out[(size_t)(p0 + pl) * Dd + h * 16 + dd0] = r;
}

// ---------------------------------------------------------------------------
extern "C" void kernel_launch(void* const* d_in, const int* in_sizes, int n_in,
                              void* d_out, int out_size)
{
    const float* aq    = (const float*)d_in[0];
    const float* anb   = (const float*)d_in[1];
    const float* ldist = (const float*)d_in[2];
    const float* maskp = (const float*)d_in[3];
    const float* Wq    = (const float*)d_in[4];
    const float* bq    = (const float*)d_in[5];
    const float* Wk    = (const float*)d_in[6];
    const float* bk    = (const float*)d_in[7];
    const float* Wv    = (const float*)d_in[8];
    const float* bv    = (const float*)d_in[9];
    const float* Wf    = (const float*)d_in[10];
    const float* bf    = (const float*)d_in[11];

    float* out = (float*)d_out;
    const size_t attn_elems = (size_t)NP * Hh * Nn;   // 4194304
    const size_t ctx_elems  = (size_t)NP * Dd;        // 2097152
    float* attn_out = nullptr;
    float* ctx_out  = nullptr;
    if ((size_t)out_size >= attn_elems + ctx_elems) { attn_out = out; ctx_out = out + attn_elems; }
    else if ((size_t)out_size == attn_elems)        { attn_out = out; }
    else                                            { ctx_out = out; }

    const int SM1 = (128 * 132 + 32 * 132 + 128) * 4;   // 84992
    const int SM2 = 14272 * 4;                          // 57088
    const int SM3 = 25024 * 4;                          // 100096

    cudaFuncSetAttribute(k_query, cudaFuncAttributeMaxDynamicSharedMemorySize, SM1);
    cudaFuncSetAttribute(k_main,  cudaFuncAttributeMaxDynamicSharedMemorySize, SM2);
    cudaFuncSetAttribute(k_ctx,   cudaFuncAttributeMaxDynamicSharedMemorySize, SM3);

    k_query<<<NP / 32, 256, SM1>>>(aq, Wq, bq);
    k_main<<<NP / 8, 256, SM2>>>(anb, ldist, maskp, Wk, bk, Wf, bf, attn_out);
    if (ctx_out)
        k_ctx<<<NP / 8, 256, SM3>>>(Wv, bv, ctx_out);
}

// round 8
// speedup vs baseline: 1.0782x; 1.0782x over previous
#include <cuda_runtime.h>
#include <cuda_bf16.h>
#include <cstdint>

// Problem constants
#define Bb   16
#define Cc   1024
#define Nn   32
#define Hh   8
#define Dd   128
#define NP   (Bb*Cc)          // 16384 (b,c) pairs
#define QSCALE 0.25f          // Dh^-0.5 = 16^-0.5

// Scratch (device globals — no runtime allocation allowed)
__device__ float g_query[(size_t)NP * Dd];           // 8 MB
__device__ float g_wsum[(size_t)NP * Hh * Dd];       // 64 MB
__device__ float g_asum[(size_t)NP * Hh];            // 512 KB

// ---- packed fp32x2 helpers (Blackwell FFMA2) -------------------------------
typedef unsigned long long ull;
__device__ __forceinline__ ull fma2(ull a, ull b, ull c) {
    ull d; asm("fma.rn.f32x2 %0, %1, %2, %3;" : "=l"(d) : "l"(a), "l"(b), "l"(c));
    return d;
}
__device__ __forceinline__ ull pk2(float lo, float hi) {
    ull r; asm("mov.b64 %0, {%1, %2};" : "=l"(r) : "f"(lo), "f"(hi)); return r;
}
__device__ __forceinline__ float2 upk2(ull v) {
    float2 r; asm("mov.b64 {%0, %1}, %2;" : "=f"(r.x), "=f"(r.y) : "l"(v)); return r;
}
#define U64(d) __double_as_longlong(d)

// ---------------------------------------------------------------------------
// K2 (fused with K1): per 8-pair block:
//   load aq -> 4 Wq quarter-stages -> query (+bq) -> g_query
//   4 Wk quarter-stages -> qk_s ; eb bias
//   per pair: gated an -> energy partials -> softmax -> wsum  (R3 structure)
// smem = 15328 floats = 61312 B  -> 3 CTAs/SM
// ---------------------------------------------------------------------------
__global__ __launch_bounds__(256, 3) void k_main(const float* __restrict__ aq,
                                                 const float* __restrict__ anb,
                                                 const float* __restrict__ ldist,
                                                 const float* __restrict__ maskp,
                                                 const float* __restrict__ Wq,
                                                 const float* __restrict__ bq,
                                                 const float* __restrict__ Wk,
                                                 const float* __restrict__ bk,
                                                 const float* __restrict__ Wf,
                                                 const float* __restrict__ bf,
                                                 float* __restrict__ attn_out)
{
    extern __shared__ float sm[];
    // persistent
    float* qk_s = sm;                    // 8p*8h rows * 132 = 8448
    float* eb_s = sm + 8448;             // 64
    float* U    = sm + 8512;             // union (6816 floats)
    // phase 1 view
    float* Wst_s   = U;                  // weight stage: max(32*132, 128*36) = 4608
    float* aq_s    = U + 4608;           // 8*132 = 1056
    float* query_s = U + 5664;           // 8*128 = 1024
    float* bk_s    = U + 6688;           // 128
    // phase 2 view
    float* an_s   = U;                   // 32*132 = 4224
    float* epart  = U + 4224;            // 8w*8h*32n = 2048
    float* attn_s = U + 6272;            // 32*12 = 384 [n*12 + h]

    const int t = threadIdx.x;
    const int p0 = blockIdx.x * 8;
    const int w = t >> 5, lane = t & 31;

    // per-thread constant gate params (thread only ever touches e = 4*(t&31)..+3)
    const float4 Wf4 = ((const float4*)Wf)[t & 31];
    const float4 bf4 = ((const float4*)bf)[t & 31];

    if (t < 128) bk_s[t] = bk[t];
    {   // aq for 8 pairs (1024 floats = 256 float4), pitch 132
        int pl = t >> 5, e4 = t & 31;
        float4 v = ((const float4*)(aq + (size_t)p0 * Dd))[t];
        *(float4*)&aq_s[pl * 132 + e4 * 4] = v;
    }

    // ---- query projection: 4 stages over f-rows of Wq (32 f x 128 d each)
    // thread = (p = w, d4 = lane); acc packed over d
    {
        ull accq0 = 0ULL, accq1 = 0ULL;
        const int pq = w, d0 = lane * 4;
        #pragma unroll
        for (int s = 0; s < 4; s++) {
            __syncthreads();   // s=0: covers aq/bk stores; s>0: Wst reuse
            #pragma unroll
            for (int j = 0; j < 4; j++) {
                int i4 = t + j * 256;               // 0..1023
                int fl = i4 >> 5, d4 = i4 & 31;
                float4 v = ((const float4*)Wq)[(s * 32 + fl) * 32 + d4];
                *(float4*)&Wst_s[fl * 132 + d4 * 4] = v;
            }
            __syncthreads();
            #pragma unroll 8
            for (int fl = 0; fl < 32; fl++) {
                float a = aq_s[pq * 132 + s * 32 + fl];       // broadcast
                ull a2 = pk2(a, a);
                double2 wv = *(double2*)&Wst_s[fl * 132 + d0]; // LDS.128 cf
                accq0 = fma2(a2, U64(wv.x), accq0);
                accq1 = fma2(a2, U64(wv.y), accq1);
            }
        }
        float4 b4 = __ldg(&((const float4*)bq)[lane]);
        float2 lo = upk2(accq0), hi = upk2(accq1);
        float4 r = { lo.x + b4.x, lo.y + b4.y, hi.x + b4.z, hi.y + b4.w };
        *(float4*)&query_s[pq * 128 + d0] = r;
        *(float4*)&g_query[(size_t)(p0 + pq) * Dd + d0] = r;
    }

    // ---- qk: 4 quarter-stages of Wk, each covers 2 heads (32 out-dims)
    const int e_col = t & 127, hl = t >> 7;
    #pragma unroll
    for (int s = 0; s < 4; s++) {
        __syncthreads();   // s=0: covers query_s stores; s>0: Wst reuse
        #pragma unroll
        for (int j = 0; j < 4; j++) {
            int idx = t + j * 256;                  // 0..1023
            int e = idx >> 3, q = idx & 7;          // 8 float4 per e-row
            float4 v = ((const float4*)Wk)[e * 32 + s * 8 + q];
            *(float4*)&Wst_s[e * 36 + q * 4] = v;
        }
        __syncthreads();
        const int h = s * 2 + hl;
        ull wk2[8];
        #pragma unroll
        for (int i = 0; i < 4; i++) {
            double2 w2 = *(double2*)&Wst_s[e_col * 36 + hl * 16 + i * 4];
            wk2[i * 2 + 0] = U64(w2.x);
            wk2[i * 2 + 1] = U64(w2.y);
        }
        #pragma unroll
        for (int p = 0; p < 8; p++) {
            ull acc2 = 0ULL;
            #pragma unroll
            for (int i = 0; i < 4; i++) {
                double2 q2 = *(double2*)&query_s[p * 128 + h * 16 + i * 4]; // bcast
                acc2 = fma2(wk2[i * 2 + 0], U64(q2.x), acc2);
                acc2 = fma2(wk2[i * 2 + 1], U64(q2.y), acc2);
            }
            float2 a = upk2(acc2);
            qk_s[(p * 8 + h) * 132 + e_col] = (a.x + a.y) * QSCALE;
        }
    }
    __syncthreads();
    // energy bias eb[p,h] = scaled q . bk  (query_s/bk_s still valid)
    if (t < 64) {
        int p = t >> 3, h = t & 7;
        float acc = 0.f;
        #pragma unroll
        for (int dd = 0; dd < 16; dd++)
            acc += query_s[p * 128 + h * 16 + dd] * bk_s[h * 16 + dd];
        eb_s[t] = acc * QSCALE;
    }
    __syncthreads();

    // prefetch for pair 0
    float4 pf[4]; float pfd[4]; float pm;
    {
        const float4* anp = (const float4*)(anb + (size_t)p0 * (Nn * Dd));
        #pragma unroll
        for (int j = 0; j < 4; j++) {
            int i4 = t + j * 256;
            pf[j] = anp[i4];
            pfd[j] = __ldg(&ldist[(size_t)p0 * Nn + (i4 >> 5)]);
        }
        pm = __ldg(&maskp[(size_t)p0 * Nn + lane]);
    }

    for (int pl = 0; pl < 8; pl++) {
        const size_t p = (size_t)(p0 + pl);
        const float pm_cur = pm;

        // ---- A: gated an: an[n,e] = anb * swish(dist*Wf+bf)
        #pragma unroll
        for (int j = 0; j < 4; j++) {
            int n = (t + j * 256) >> 5;
            float4 v = pf[j];
            float dval = pfd[j];
            float x0 = fmaf(dval, Wf4.x, bf4.x);
            float x1 = fmaf(dval, Wf4.y, bf4.y);
            float x2 = fmaf(dval, Wf4.z, bf4.z);
            float x3 = fmaf(dval, Wf4.w, bf4.w);
            float4 g;
            g.x = v.x * __fdividef(x0, 1.f + __expf(-x0));
            g.y = v.y * __fdividef(x1, 1.f + __expf(-x1));
            g.z = v.z * __fdividef(x2, 1.f + __expf(-x2));
            g.w = v.w * __fdividef(x3, 1.f + __expf(-x3));
            *(float4*)&an_s[n * 132 + (t & 31) * 4] = g;
        }
        __syncthreads();

        // prefetch next pair while B/C/D run
        if (pl < 7) {
            const float4* anp = (const float4*)(anb + (p + 1) * (Nn * Dd));
            #pragma unroll
            for (int j = 0; j < 4; j++) {
                int i4 = t + j * 256;
                pf[j] = anp[i4];
                pfd[j] = __ldg(&ldist[(p + 1) * Nn + (i4 >> 5)]);
            }
            pm = __ldg(&maskp[(p + 1) * Nn + lane]);
        }

        // ---- B: energy partials — warp w owns e-chunk [w*16,+16), lane = n
        {
            ull a2[8];
            #pragma unroll
            for (int i = 0; i < 4; i++) {
                double2 av = *(double2*)&an_s[lane * 132 + w * 16 + i * 4];
                a2[i * 2 + 0] = U64(av.x);
                a2[i * 2 + 1] = U64(av.y);
            }
            const float* qkp = &qk_s[pl * 8 * 132 + w * 16];
            #pragma unroll
            for (int h = 0; h < 8; h++) {
                ull acc2 = 0ULL;
                #pragma unroll
                for (int i = 0; i < 4; i++) {
                    double2 q2 = *(const double2*)&qkp[h * 132 + i * 4]; // bcast
                    acc2 = fma2(a2[i * 2 + 0], U64(q2.x), acc2);
                    acc2 = fma2(a2[i * 2 + 1], U64(q2.y), acc2);
                }
                float2 a = upk2(acc2);
                epart[(w * 8 + h) * 32 + lane] = a.x + a.y;
            }
        }
        __syncthreads();

        // ---- C: reduce + softmax over n (no max pass): warp w = head, lane = n
        {
            const int h = w, n = lane;
            float en = eb_s[pl * 8 + h];
            #pragma unroll
            for (int wc = 0; wc < 8; wc++) en += epart[(wc * 8 + h) * 32 + n];
            en += (1.f - pm_cur) * (-1e9f);
            float ex = __expf(en);
            float exm = ex * pm_cur;
            float s = ex, smm = exm;
            #pragma unroll
            for (int o = 16; o > 0; o >>= 1) {
                s   += __shfl_xor_sync(0xffffffffu, s, o);
                smm += __shfl_xor_sync(0xffffffffu, smm, o);
            }
            float rinv = __fdividef(1.f, s);
            float at = ex * rinv;
            if (attn_out) {
                int b = (int)(p >> 10), c = (int)(p & 1023);
                attn_out[((size_t)(b * Hh + h) * Cc + c) * Nn + n] = at;
            }
            attn_s[n * 12 + h] = at * pm_cur;
            if (n == 0) g_asum[p * Hh + h] = smm * rinv;
        }
        __syncthreads();

        // ---- D: wsum[h,e] = sum_n attnm[h,n]*an[n,e]; thread = (e, h-half)
        {
            const int e = t & 127, hh = t >> 7;
            ull acc01 = 0ULL, acc23 = 0ULL;
            #pragma unroll 8
            for (int n = 0; n < 32; n++) {
                float av = an_s[n * 132 + e];                      // conflict-free
                ull av2 = pk2(av, av);
                double2 at2 = *(double2*)&attn_s[n * 12 + hh * 4]; // bcast LDS.128
                acc01 = fma2(av2, U64(at2.x), acc01);
                acc23 = fma2(av2, U64(at2.y), acc23);
            }
            float2 a01 = upk2(acc01), a23 = upk2(acc23);
            float* wout = &g_wsum[(p * Hh + hh * 4) * Dd + e];
            wout[0] = a01.x; wout[128] = a01.y; wout[256] = a23.x; wout[384] = a23.y;
        }
        __syncthreads();
    }
}

// ---------------------------------------------------------------------------
// K3: context[p, h*16+dd] = wsum[p,h,:] @ Wv[:, h*16+dd] + asum*bv + query
// 8 pairs per block. smem = 25024 floats = 100096 B -> 2 CTAs/SM
// ---------------------------------------------------------------------------
__global__ __launch_bounds__(256, 2) void k_ctx(const float* __restrict__ Wv,
                                                const float* __restrict__ bv,
                                                float* __restrict__ ctx_out)
{
    extern __shared__ float sm[];
    float* Wv_s   = sm;                  // 128*128 = 16384
    float* ws_s   = sm + 16384;          // 64 rows (8p*8h) * 132 = 8448
    float* asum_s = sm + 24832;          // 64
    float* bv_s   = sm + 24896;          // 128

    const int t = threadIdx.x;
    const int p0 = blockIdx.x * 8;

    #pragma unroll
    for (int j = 0; j < 16; j++) {
        int i4 = t + j * 256;
        ((float4*)Wv_s)[i4] = ((const float4*)Wv)[i4];
    }
    #pragma unroll
    for (int j = 0; j < 8; j++) {
        int i4 = t + j * 256;
        int row = i4 >> 5, e4 = i4 & 31;
        float4 v = ((const float4*)(g_wsum + (size_t)p0 * Hh * Dd))[i4];
        *(float4*)&ws_s[row * 132 + e4 * 4] = v;
    }
    if (t < 64)  asum_s[t] = g_asum[(size_t)p0 * Hh + t];
    if (t < 128) bv_s[t] = bv[t];
    __syncthreads();

    const int pl = t >> 5, lane = t & 31;
    const int h = lane >> 2, dd0 = (lane & 3) * 4;
    const float* wr  = &ws_s[(pl * 8 + h) * 132];
    const float* wvp = &Wv_s[h * 16 + dd0];
    ull acc01 = 0ULL, acc23 = 0ULL;
    #pragma unroll 8
    for (int e = 0; e < 128; e++) {
        float s = wr[e];                           // 8 banks, 4-way bcast
        ull s2 = pk2(s, s);
        double2 wv = *(const double2*)&wvp[e * 128];
        acc01 = fma2(s2, U64(wv.x), acc01);
        acc23 = fma2(s2, U64(wv.y), acc23);
    }
    float as = asum_s[pl * 8 + h];
    float4 b4 = *(const float4*)&bv_s[h * 16 + dd0];
    float4 q4 = *(const float4*)&g_query[(size_t)(p0 + pl) * Dd + h * 16 + dd0];
    float2 a01 = upk2(acc01), a23 = upk2(acc23);
    float4 r;
    r.x = a01.x + as * b4.x + q4.x;
    r.y = a01.y + as * b4.y + q4.y;
    r.z = a23.x + as * b4.z + q4.z;
    r.w = a23.y + as * b4.w + q4.w;
    *(float4*)&ctx_out[(size_t)(p0 + pl) * Dd + h * 16 + dd0] = r;
}

// ---------------------------------------------------------------------------
extern "C" void kernel_launch(void* const* d_in, const int* in_sizes, int n_in,
                              void* d_out, int out_size)
{
    const float* aq    = (const float*)d_in[0];
    const float* anb   = (const float*)d_in[1];
    const float* ldist = (const float*)d_in[2];
    const float* maskp = (const float*)d_in[3];
    const float* Wq    = (const float*)d_in[4];
    const float* bq    = (const float*)d_in[5];
    const float* Wk    = (const float*)d_in[6];
    const float* bk    = (const float*)d_in[7];
    const float* Wv    = (const float*)d_in[8];
    const float* bv    = (const float*)d_in[9];
    const float* Wf    = (const float*)d_in[10];
    const float* bf    = (const float*)d_in[11];

    float* out = (float*)d_out;
    const size_t attn_elems = (size_t)NP * Hh * Nn;   // 4194304
    const size_t ctx_elems  = (size_t)NP * Dd;        // 2097152
    float* attn_out = nullptr;
    float* ctx_out  = nullptr;
    if ((size_t)out_size >= attn_elems + ctx_elems) { attn_out = out; ctx_out = out + attn_elems; }
    else if ((size_t)out_size == attn_elems)        { attn_out = out; }
    else                                            { ctx_out = out; }

    const int SM2 = 15328 * 4;                          // 61312
    const int SM3 = 25024 * 4;                          // 100096

    cudaFuncSetAttribute(k_main, cudaFuncAttributeMaxDynamicSharedMemorySize, SM2);
    cudaFuncSetAttribute(k_ctx,  cudaFuncAttributeMaxDynamicSharedMemorySize, SM3);

    k_main<<<NP / 8, 256, SM2>>>(aq, anb, ldist, maskp, Wq, bq, Wk, bk, Wf, bf, attn_out);
    if (ctx_out)
        k_ctx<<<NP / 8, 256, SM3>>>(Wv, bv, ctx_out);
}

// round 9
// speedup vs baseline: 1.1212x; 1.0399x over previous
#include <cuda_runtime.h>
#include <cuda_bf16.h>
#include <cstdint>

// Problem constants
#define Bb   16
#define Cc   1024
#define Nn   32
#define Hh   8
#define Dd   128
#define NP   (Bb*Cc)          // 16384 (b,c) pairs
#define QSCALE 0.25f          // Dh^-0.5 = 16^-0.5

// Scratch (device globals — no runtime allocation allowed)
__device__ float g_query[(size_t)NP * Dd];           // 8 MB
__device__ float g_wsum[(size_t)NP * Hh * Dd];       // 64 MB
__device__ float g_asum[(size_t)NP * Hh];            // 512 KB

// ---- packed fp32x2 helpers (Blackwell FFMA2) -------------------------------
typedef unsigned long long ull;
__device__ __forceinline__ ull fma2(ull a, ull b, ull c) {
    ull d; asm("fma.rn.f32x2 %0, %1, %2, %3;" : "=l"(d) : "l"(a), "l"(b), "l"(c));
    return d;
}
__device__ __forceinline__ ull pk2(float lo, float hi) {
    ull r; asm("mov.b64 %0, {%1, %2};" : "=l"(r) : "f"(lo), "f"(hi)); return r;
}
__device__ __forceinline__ float2 upk2(ull v) {
    float2 r; asm("mov.b64 {%0, %1}, %2;" : "=f"(r.x), "=f"(r.y) : "l"(v)); return r;
}
#define U64(d) __double_as_longlong(d)

// ---------------------------------------------------------------------------
// K1: query[p,d] = atom_query[p,:] @ Wq + bq      (32 pairs per block)
// ---------------------------------------------------------------------------
__global__ __launch_bounds__(256) void k_query(const float* __restrict__ aq,
                                               const float* __restrict__ Wq,
                                               const float* __restrict__ bq)
{
    extern __shared__ float sm[];
    float* Wq_s = sm;                  // 128*132
    float* aq_s = Wq_s + 128 * 132;    // 32*132
    float* bq_s = aq_s + 32 * 132;     // 128
    const int t = threadIdx.x;

    #pragma unroll
    for (int j = 0; j < 16; j++) {
        int i4 = t + j * 256;
        int f = i4 >> 5, d4 = i4 & 31;
        float4 v = ((const float4*)Wq)[i4];
        *(float4*)&Wq_s[f * 132 + d4 * 4] = v;
    }
    if (t < 128) bq_s[t] = bq[t];

    const int p0 = blockIdx.x * 32;
    #pragma unroll
    for (int j = 0; j < 4; j++) {
        int i4 = t + j * 256;
        int pl = i4 >> 5, e4 = i4 & 31;
        float4 v = ((const float4*)(aq + (size_t)p0 * Dd))[i4];
        *(float4*)&aq_s[pl * 132 + e4 * 4] = v;
    }
    __syncthreads();

    const int w = t >> 5, lane = t & 31;
    const int pl0 = w * 4, d0 = lane * 4;
    ull acc[4][2];
    #pragma unroll
    for (int k = 0; k < 4; k++) { acc[k][0] = 0ULL; acc[k][1] = 0ULL; }
    #pragma unroll 4
    for (int f = 0; f < 128; f++) {
        double2 wv = *(double2*)&Wq_s[f * 132 + d0];     // LDS.128
        #pragma unroll
        for (int k = 0; k < 4; k++) {
            float a = aq_s[(pl0 + k) * 132 + f];         // broadcast
            ull a2 = pk2(a, a);
            acc[k][0] = fma2(a2, U64(wv.x), acc[k][0]);
            acc[k][1] = fma2(a2, U64(wv.y), acc[k][1]);
        }
    }
    float4 b4 = *(float4*)&bq_s[d0];
    #pragma unroll
    for (int k = 0; k < 4; k++) {
        float2 lo = upk2(acc[k][0]), hi = upk2(acc[k][1]);
        float4 r = { lo.x + b4.x, lo.y + b4.y, hi.x + b4.z, hi.y + b4.w };
        *(float4*)&g_query[(size_t)(p0 + pl0 + k) * Dd + d0] = r;
    }
}

// ---------------------------------------------------------------------------
// K2: per 8-pair batch: qk (Wk staged in 2 halves, union smem), then per pair:
//     prefetched gated an -> energy (f32x2) -> softmax -> wsum (f32x2).
// smem = 18400 floats = 73600 B  -> 3 CTAs/SM          (exact R3 kernel)
// ---------------------------------------------------------------------------
__global__ __launch_bounds__(256, 3) void k_main(const float* __restrict__ anb,
                                                 const float* __restrict__ ldist,
                                                 const float* __restrict__ maskp,
                                                 const float* __restrict__ Wk,
                                                 const float* __restrict__ bk,
                                                 const float* __restrict__ Wf,
                                                 const float* __restrict__ bf,
                                                 float* __restrict__ attn_out)
{
    extern __shared__ float sm[];
    // persistent
    float* qk_s = sm;                    // 8p*8h*128e = 8192   [(pl*8+h)*128 + e]
    float* eb_s = sm + 8192;             // 64
    float* Wf_s = sm + 8256;             // 128
    float* bf_s = sm + 8384;             // 128
    float* U    = sm + 8512;             // union (9888 floats)
    // phase 1 view
    float* Wk_s    = U;                  // 128e * 68 = 8704 (half of d staged)
    float* query_s = U + 8704;           // 8*132 = 1056
    float* bk_s    = U + 9760;           // 128
    // phase 2 view
    float* an_s   = U;                   // 32*132 = 4224
    float* epart  = U + 4224;            // 8w*8h*32n = 2048
    float* attn_s = U + 6272;            // 32*12 = 384  [n*12 + h]

    const int t = threadIdx.x;
    const int p0 = blockIdx.x * 8;

    if (t < 128) { Wf_s[t] = Wf[t]; bf_s[t] = bf[t]; bk_s[t] = bk[t]; }
    {   // query for 8 pairs (1024 floats = 256 float4)
        int pl = t >> 5, e4 = t & 31;
        float4 v = ((const float4*)(g_query + (size_t)p0 * Dd))[t];
        *(float4*)&query_s[pl * 132 + e4 * 4] = v;
    }

    // ---- qk: two half-stages of Wk (d<64 -> heads 0..3, d>=64 -> heads 4..7)
    const int e_col = t & 127, h2 = t >> 7;
    #pragma unroll
    for (int half = 0; half < 2; half++) {
        #pragma unroll
        for (int j = 0; j < 8; j++) {
            int i4 = t + j * 256;                  // 0..2047
            int e = i4 >> 4, d4 = i4 & 15;
            float4 v = ((const float4*)Wk)[e * 32 + half * 16 + d4];
            *(float4*)&Wk_s[e * 68 + d4 * 4] = v;
        }
        __syncthreads();
        ull wk2[2][8];
        #pragma unroll
        for (int hl = 0; hl < 2; hl++)
            #pragma unroll
            for (int i = 0; i < 4; i++) {
                double2 w2 = *(double2*)&Wk_s[e_col * 68 + (h2 * 2 + hl) * 16 + i * 4];
                wk2[hl][i * 2 + 0] = U64(w2.x);
                wk2[hl][i * 2 + 1] = U64(w2.y);
            }
        #pragma unroll
        for (int p = 0; p < 8; p++) {
            #pragma unroll
            for (int hl = 0; hl < 2; hl++) {
                const int h = half * 4 + h2 * 2 + hl;
                ull acc2 = 0ULL;
                #pragma unroll
                for (int i = 0; i < 4; i++) {
                    double2 q2 = *(double2*)&query_s[p * 132 + h * 16 + i * 4]; // bcast
                    acc2 = fma2(wk2[hl][i * 2 + 0], U64(q2.x), acc2);
                    acc2 = fma2(wk2[hl][i * 2 + 1], U64(q2.y), acc2);
                }
                float2 a = upk2(acc2);
                qk_s[(p * 8 + h) * 128 + e_col] = (a.x + a.y) * QSCALE;
            }
        }
        __syncthreads();
    }
    // energy bias eb[p,h] = scaled q . bk  (query_s/bk_s still valid)
    if (t < 64) {
        int p = t >> 3, h = t & 7;
        float acc = 0.f;
        #pragma unroll
        for (int dd = 0; dd < 16; dd++)
            acc += query_s[p * 132 + h * 16 + dd] * bk_s[h * 16 + dd];
        eb_s[t] = acc * QSCALE;
    }
    __syncthreads();

    const int w = t >> 5, lane = t & 31;

    // prefetch buffers for pair pl
    float4 pf[4]; float pfd[4]; float pm;
    {
        const float4* anp = (const float4*)(anb + (size_t)p0 * (Nn * Dd));
        #pragma unroll
        for (int j = 0; j < 4; j++) {
            int i4 = t + j * 256;
            pf[j] = anp[i4];
            pfd[j] = __ldg(&ldist[(size_t)p0 * Nn + (i4 >> 5)]);
        }
        pm = __ldg(&maskp[(size_t)p0 * Nn + lane]);
    }

    for (int pl = 0; pl < 8; pl++) {
        const size_t p = (size_t)(p0 + pl);
        const float pm_cur = pm;

        // ---- A: gated an from prefetched regs: an[n,e] = anb * swish(d*Wf+bf)
        #pragma unroll
        for (int j = 0; j < 4; j++) {
            int i4 = t + j * 256;
            int n = i4 >> 5, e4 = i4 & 31;
            float4 v = pf[j];
            float dval = pfd[j];
            int e = e4 * 4;
            float x0 = fmaf(dval, Wf_s[e + 0], bf_s[e + 0]);
            float x1 = fmaf(dval, Wf_s[e + 1], bf_s[e + 1]);
            float x2 = fmaf(dval, Wf_s[e + 2], bf_s[e + 2]);
            float x3 = fmaf(dval, Wf_s[e + 3], bf_s[e + 3]);
            float4 g;
            g.x = v.x * __fdividef(x0, 1.f + __expf(-x0));
            g.y = v.y * __fdividef(x1, 1.f + __expf(-x1));
            g.z = v.z * __fdividef(x2, 1.f + __expf(-x2));
            g.w = v.w * __fdividef(x3, 1.f + __expf(-x3));
            *(float4*)&an_s[n * 132 + e] = g;
        }
        __syncthreads();

        // prefetch next pair while B/C/D run
        if (pl < 7) {
            const float4* anp = (const float4*)(anb + (p + 1) * (Nn * Dd));
            #pragma unroll
            for (int j = 0; j < 4; j++) {
                int i4 = t + j * 256;
                pf[j] = anp[i4];
                pfd[j] = __ldg(&ldist[(p + 1) * Nn + (i4 >> 5)]);
            }
            pm = __ldg(&maskp[(p + 1) * Nn + lane]);
        }

        // ---- B: energy partials — warp w owns e-chunk [w*16,+16), lane = n
        {
            ull a2[8];
            #pragma unroll
            for (int i = 0; i < 4; i++) {
                double2 av = *(double2*)&an_s[lane * 132 + w * 16 + i * 4];
                a2[i * 2 + 0] = U64(av.x);
                a2[i * 2 + 1] = U64(av.y);
            }
            const float* qkp = &qk_s[pl * 8 * 128 + w * 16];
            #pragma unroll
            for (int h = 0; h < 8; h++) {
                ull acc2 = 0ULL;
                #pragma unroll
                for (int i = 0; i < 4; i++) {
                    double2 q2 = *(const double2*)&qkp[h * 128 + i * 4]; // bcast
                    acc2 = fma2(a2[i * 2 + 0], U64(q2.x), acc2);
                    acc2 = fma2(a2[i * 2 + 1], U64(q2.y), acc2);
                }
                float2 a = upk2(acc2);
                epart[(w * 8 + h) * 32 + lane] = a.x + a.y;
            }
        }
        __syncthreads();

        // ---- C: reduce + softmax over n (no max pass): warp w = head, lane = n
        {
            const int h = w, n = lane;
            float en = eb_s[pl * 8 + h];
            #pragma unroll
            for (int wc = 0; wc < 8; wc++) en += epart[(wc * 8 + h) * 32 + n];
            en += (1.f - pm_cur) * (-1e9f);
            float ex = __expf(en);
            float exm = ex * pm_cur;
            float s = ex, smm = exm;
            #pragma unroll
            for (int o = 16; o > 0; o >>= 1) {
                s   += __shfl_xor_sync(0xffffffffu, s, o);
                smm += __shfl_xor_sync(0xffffffffu, smm, o);
            }
            float rinv = __fdividef(1.f, s);
            float at = ex * rinv;
            if (attn_out) {
                int b = (int)(p >> 10), c = (int)(p & 1023);
                attn_out[((size_t)(b * Hh + h) * Cc + c) * Nn + n] = at;
            }
            attn_s[n * 12 + h] = at * pm_cur;
            if (n == 0) g_asum[p * Hh + h] = smm * rinv;
        }
        __syncthreads();

        // ---- D: wsum[h,e] = sum_n attnm[h,n]*an[n,e]; thread = (e, h-half)
        {
            const int e = t & 127, hh = t >> 7;
            ull acc01 = 0ULL, acc23 = 0ULL;
            #pragma unroll 8
            for (int n = 0; n < 32; n++) {
                float av = an_s[n * 132 + e];                      // conflict-free
                ull av2 = pk2(av, av);
                double2 at2 = *(double2*)&attn_s[n * 12 + hh * 4]; // bcast LDS.128
                acc01 = fma2(av2, U64(at2.x), acc01);
                acc23 = fma2(av2, U64(at2.y), acc23);
            }
            float2 a01 = upk2(acc01), a23 = upk2(acc23);
            float* wout = &g_wsum[(p * Hh + hh * 4) * Dd + e];
            wout[0] = a01.x; wout[128] = a01.y; wout[256] = a23.x; wout[384] = a23.y;
        }
        __syncthreads();
    }
}

// ---------------------------------------------------------------------------
// K3 v2: context[p, h*16+dd] = wsum[p,h,:] @ Wv[:, h*16+dd] + asum*bv + query
// 32 pairs per block, 1 CTA/SM. Each thread accumulates 4 pairs at fixed
// (h, dd0): Wv LDS.128 amortized 4x; ws reads are broadcast-dedup LDS.128
// (pitch 132 tiles all 32 banks across the 8 h-rows -> 1 cyc/instr).
// smem = 50560 floats = 202240 B
// ---------------------------------------------------------------------------
__global__ __launch_bounds__(256, 1) void k_ctx(const float* __restrict__ Wv,
                                                const float* __restrict__ bv,
                                                float* __restrict__ ctx_out)
{
    extern __shared__ float sm[];
    float* Wv_s   = sm;                  // 128*128 = 16384
    float* ws_s   = sm + 16384;          // 256 rows (32p*8h) * 132 = 33792
    float* asum_s = sm + 50176;          // 256
    float* bv_s   = sm + 50432;          // 128

    const int t = threadIdx.x;
    const int p0 = blockIdx.x * 32;

    #pragma unroll
    for (int j = 0; j < 16; j++) {
        int i4 = t + j * 256;
        ((float4*)Wv_s)[i4] = ((const float4*)Wv)[i4];
    }
    #pragma unroll
    for (int j = 0; j < 32; j++) {
        int i4 = t + j * 256;                       // 8192 float4 = 32p*8h*32
        int row = i4 >> 5, e4 = i4 & 31;
        float4 v = ((const float4*)(g_wsum + (size_t)p0 * Hh * Dd))[i4];
        *(float4*)&ws_s[row * 132 + e4 * 4] = v;
    }
    asum_s[t] = g_asum[(size_t)p0 * Hh + t];        // 256 = 32p*8h
    if (t < 128) bv_s[t] = bv[t];
    __syncthreads();

    const int w = t >> 5, lane = t & 31;
    const int h = lane >> 2, dd0 = (lane & 3) * 4;
    // thread accumulates pairs pl = w + 8k, k = 0..3
    const float* wvp = &Wv_s[h * 16 + dd0];
    ull a01[4] = {0ULL, 0ULL, 0ULL, 0ULL};
    ull a23[4] = {0ULL, 0ULL, 0ULL, 0ULL};

    #pragma unroll 8
    for (int e4 = 0; e4 < 32; e4++) {
        float skk[4][4];
        #pragma unroll
        for (int k = 0; k < 4; k++)
            *(float4*)skk[k] = *(float4*)&ws_s[((w + 8 * k) * 8 + h) * 132 + e4 * 4];
        #pragma unroll
        for (int j = 0; j < 4; j++) {
            double2 wv = *(const double2*)&wvp[(e4 * 4 + j) * 128];
            #pragma unroll
            for (int k = 0; k < 4; k++) {
                ull s2 = pk2(skk[k][j], skk[k][j]);
                a01[k] = fma2(s2, U64(wv.x), a01[k]);
                a23[k] = fma2(s2, U64(wv.y), a23[k]);
            }
        }
    }

    float4 b4 = *(const float4*)&bv_s[h * 16 + dd0];
    #pragma unroll
    for (int k = 0; k < 4; k++) {
        const int pl = w + 8 * k;
        float as = asum_s[pl * 8 + h];
        float4 q4 = *(const float4*)&g_query[(size_t)(p0 + pl) * Dd + h * 16 + dd0];
        float2 lo = upk2(a01[k]), hi = upk2(a23[k]);
        float4 r;
        r.x = lo.x + as * b4.x + q4.x;
        r.y = lo.y + as * b4.y + q4.y;
        r.z = hi.x + as * b4.z + q4.z;
        r.w = hi.y + as * b4.w + q4.w;
        *(float4*)&ctx_out[(size_t)(p0 + pl) * Dd + h * 16 + dd0] = r;
    }
}

// ---------------------------------------------------------------------------
extern "C" void kernel_launch(void* const* d_in, const int* in_sizes, int n_in,
                              void* d_out, int out_size)
{
    const float* aq    = (const float*)d_in[0];
    const float* anb   = (const float*)d_in[1];
    const float* ldist = (const float*)d_in[2];
    const float* maskp = (const float*)d_in[3];
    const float* Wq    = (const float*)d_in[4];
    const float* bq    = (const float*)d_in[5];
    const float* Wk    = (const float*)d_in[6];
    const float* bk    = (const float*)d_in[7];
    const float* Wv    = (const float*)d_in[8];
    const float* bv    = (const float*)d_in[9];
    const float* Wf    = (const float*)d_in[10];
    const float* bf    = (const float*)d_in[11];

    float* out = (float*)d_out;
    const size_t attn_elems = (size_t)NP * Hh * Nn;   // 4194304
    const size_t ctx_elems  = (size_t)NP * Dd;        // 2097152
    float* attn_out = nullptr;
    float* ctx_out  = nullptr;
    if ((size_t)out_size >= attn_elems + ctx_elems) { attn_out = out; ctx_out = out + attn_elems; }
    else if ((size_t)out_size == attn_elems)        { attn_out = out; }
    else                                            { ctx_out = out; }

    const int SM1 = (128 * 132 + 32 * 132 + 128) * 4;   // 84992
    const int SM2 = 18400 * 4;                          // 73600
    const int SM3 = 50560 * 4;                          // 202240

    cudaFuncSetAttribute(k_query, cudaFuncAttributeMaxDynamicSharedMemorySize, SM1);
    cudaFuncSetAttribute(k_main,  cudaFuncAttributeMaxDynamicSharedMemorySize, SM2);
    cudaFuncSetAttribute(k_ctx,   cudaFuncAttributeMaxDynamicSharedMemorySize, SM3);

    k_query<<<NP / 32, 256, SM1>>>(aq, Wq, bq);
    k_main<<<NP / 8, 256, SM2>>>(anb, ldist, maskp, Wk, bk, Wf, bf, attn_out);
    if (ctx_out)
        k_ctx<<<NP / 32, 256, SM3>>>(Wv, bv, ctx_out);
}

// round 10
// speedup vs baseline: 1.2076x; 1.0770x over previous
#include <cuda_runtime.h>
#include <cuda_bf16.h>
#include <cstdint>

// Problem constants
#define Bb   16
#define Cc   1024
#define Nn   32
#define Hh   8
#define Dd   128
#define NP   (Bb*Cc)          // 16384 (b,c) pairs
#define QSCALE 0.25f          // Dh^-0.5 = 16^-0.5
#define PB   4                // pairs per k_main block

// Scratch (device globals — no runtime allocation allowed)
__device__ float g_query[(size_t)NP * Dd];           // 8 MB
__device__ float g_wsum[(size_t)NP * Hh * Dd];       // 64 MB
__device__ float g_asum[(size_t)NP * Hh];            // 512 KB

// ---- packed fp32x2 helpers (Blackwell FFMA2) -------------------------------
typedef unsigned long long ull;
__device__ __forceinline__ ull fma2(ull a, ull b, ull c) {
    ull d; asm("fma.rn.f32x2 %0, %1, %2, %3;" : "=l"(d) : "l"(a), "l"(b), "l"(c));
    return d;
}
__device__ __forceinline__ ull pk2(float lo, float hi) {
    ull r; asm("mov.b64 %0, {%1, %2};" : "=l"(r) : "f"(lo), "f"(hi)); return r;
}
__device__ __forceinline__ float2 upk2(ull v) {
    float2 r; asm("mov.b64 {%0, %1}, %2;" : "=f"(r.x), "=f"(r.y) : "l"(v)); return r;
}
#define U64(d) __double_as_longlong(d)

// ---------------------------------------------------------------------------
// K1: query[p,d] = atom_query[p,:] @ Wq + bq      (32 pairs per block)
// ---------------------------------------------------------------------------
__global__ __launch_bounds__(256) void k_query(const float* __restrict__ aq,
                                               const float* __restrict__ Wq,
                                               const float* __restrict__ bq)
{
    extern __shared__ float sm[];
    float* Wq_s = sm;                  // 128*132
    float* aq_s = Wq_s + 128 * 132;    // 32*132
    float* bq_s = aq_s + 32 * 132;     // 128
    const int t = threadIdx.x;

    #pragma unroll
    for (int j = 0; j < 16; j++) {
        int i4 = t + j * 256;
        int f = i4 >> 5, d4 = i4 & 31;
        float4 v = ((const float4*)Wq)[i4];
        *(float4*)&Wq_s[f * 132 + d4 * 4] = v;
    }
    if (t < 128) bq_s[t] = bq[t];

    const int p0 = blockIdx.x * 32;
    #pragma unroll
    for (int j = 0; j < 4; j++) {
        int i4 = t + j * 256;
        int pl = i4 >> 5, e4 = i4 & 31;
        float4 v = ((const float4*)(aq + (size_t)p0 * Dd))[i4];
        *(float4*)&aq_s[pl * 132 + e4 * 4] = v;
    }
    __syncthreads();

    const int w = t >> 5, lane = t & 31;
    const int pl0 = w * 4, d0 = lane * 4;
    ull acc[4][2];
    #pragma unroll
    for (int k = 0; k < 4; k++) { acc[k][0] = 0ULL; acc[k][1] = 0ULL; }
    #pragma unroll 4
    for (int f = 0; f < 128; f++) {
        double2 wv = *(double2*)&Wq_s[f * 132 + d0];     // LDS.128
        #pragma unroll
        for (int k = 0; k < 4; k++) {
            float a = aq_s[(pl0 + k) * 132 + f];         // broadcast
            ull a2 = pk2(a, a);
            acc[k][0] = fma2(a2, U64(wv.x), acc[k][0]);
            acc[k][1] = fma2(a2, U64(wv.y), acc[k][1]);
        }
    }
    float4 b4 = *(float4*)&bq_s[d0];
    #pragma unroll
    for (int k = 0; k < 4; k++) {
        float2 lo = upk2(acc[k][0]), hi = upk2(acc[k][1]);
        float4 r = { lo.x + b4.x, lo.y + b4.y, hi.x + b4.z, hi.y + b4.w };
        *(float4*)&g_query[(size_t)(p0 + pl0 + k) * Dd + d0] = r;
    }
}

// ---------------------------------------------------------------------------
// K2 v4: 4 pairs per block, 4 CTAs/SM (32 warps). Wk in 4 quarter-stages,
// Wf/bf in registers. Per pair: R3's A/B/C/D phases unchanged.
// smem = 10784 floats = 43136 B
// ---------------------------------------------------------------------------
__global__ __launch_bounds__(256, 4) void k_main(const float* __restrict__ anb,
                                                 const float* __restrict__ ldist,
                                                 const float* __restrict__ maskp,
                                                 const float* __restrict__ Wk,
                                                 const float* __restrict__ bk,
                                                 const float* __restrict__ Wf,
                                                 const float* __restrict__ bf,
                                                 float* __restrict__ attn_out)
{
    extern __shared__ float sm[];
    // persistent
    float* qk_s = sm;                    // 4p*8h rows * 128 = 4096
    float* eb_s = sm + 4096;             // 32
    float* U    = sm + 4128;             // union (6656 floats)
    // phase 1 view
    float* Wst_s   = U;                  // 128e * 36 = 4608 (quarter stage)
    float* query_s = U + 4608;           // 4*132 = 528
    float* bk_s    = U + 5136;           // 128
    // phase 2 view
    float* an_s   = U;                   // 32*132 = 4224
    float* epart  = U + 4224;            // 8w*8h*32n = 2048
    float* attn_s = U + 6272;            // 32*12 = 384  [n*12 + h]

    const int t = threadIdx.x;
    const int p0 = blockIdx.x * PB;
    const int w = t >> 5, lane = t & 31;

    // per-thread gate params (thread only ever touches e = 4*(t&31)..+3)
    const float4 Wf4 = ((const float4*)Wf)[t & 31];
    const float4 bf4 = ((const float4*)bf)[t & 31];

    if (t < 128) bk_s[t] = bk[t];
    if (t < 128) {   // query for 4 pairs (512 floats = 128 float4), pitch 132
        int pl = t >> 5, e4 = t & 31;
        float4 v = ((const float4*)(g_query + (size_t)p0 * Dd))[t];
        *(float4*)&query_s[pl * 132 + e4 * 4] = v;
    }

    // ---- qk: 4 quarter-stages of Wk, each covers 2 heads (32 out-dims)
    const int e_col = t & 127, hl = t >> 7;
    #pragma unroll
    for (int s = 0; s < 4; s++) {
        __syncthreads();   // s=0: covers query/bk stores; s>0: Wst reuse
        #pragma unroll
        for (int j = 0; j < 4; j++) {
            int idx = t + j * 256;                  // 0..1023
            int e = idx >> 3, q = idx & 7;          // 8 float4 per e-row
            float4 v = ((const float4*)Wk)[e * 32 + s * 8 + q];
            *(float4*)&Wst_s[e * 36 + q * 4] = v;
        }
        __syncthreads();
        const int h = s * 2 + hl;
        ull wk2[8];
        #pragma unroll
        for (int i = 0; i < 4; i++) {
            double2 w2 = *(double2*)&Wst_s[e_col * 36 + hl * 16 + i * 4];
            wk2[i * 2 + 0] = U64(w2.x);
            wk2[i * 2 + 1] = U64(w2.y);
        }
        #pragma unroll
        for (int p = 0; p < PB; p++) {
            ull acc2 = 0ULL;
            #pragma unroll
            for (int i = 0; i < 4; i++) {
                double2 q2 = *(double2*)&query_s[p * 132 + h * 16 + i * 4]; // bcast
                acc2 = fma2(wk2[i * 2 + 0], U64(q2.x), acc2);
                acc2 = fma2(wk2[i * 2 + 1], U64(q2.y), acc2);
            }
            float2 a = upk2(acc2);
            qk_s[(p * 8 + h) * 128 + e_col] = (a.x + a.y) * QSCALE;
        }
    }
    __syncthreads();
    // energy bias eb[p,h] = scaled q . bk  (query_s/bk_s still valid)
    if (t < 8 * PB) {
        int p = t >> 3, h = t & 7;
        float acc = 0.f;
        #pragma unroll
        for (int dd = 0; dd < 16; dd++)
            acc += query_s[p * 132 + h * 16 + dd] * bk_s[h * 16 + dd];
        eb_s[t] = acc * QSCALE;
    }
    __syncthreads();

    // prefetch for pair 0
    float4 pf[4]; float pfd[4]; float pm;
    {
        const float4* anp = (const float4*)(anb + (size_t)p0 * (Nn * Dd));
        #pragma unroll
        for (int j = 0; j < 4; j++) {
            int i4 = t + j * 256;
            pf[j] = anp[i4];
            pfd[j] = __ldg(&ldist[(size_t)p0 * Nn + (i4 >> 5)]);
        }
        pm = __ldg(&maskp[(size_t)p0 * Nn + lane]);
    }

    for (int pl = 0; pl < PB; pl++) {
        const size_t p = (size_t)(p0 + pl);
        const float pm_cur = pm;

        // ---- A: gated an: an[n,e] = anb * swish(dist*Wf+bf)
        #pragma unroll
        for (int j = 0; j < 4; j++) {
            int n = (t + j * 256) >> 5;
            float4 v = pf[j];
            float dval = pfd[j];
            float x0 = fmaf(dval, Wf4.x, bf4.x);
            float x1 = fmaf(dval, Wf4.y, bf4.y);
            float x2 = fmaf(dval, Wf4.z, bf4.z);
            float x3 = fmaf(dval, Wf4.w, bf4.w);
            float4 g;
            g.x = v.x * __fdividef(x0, 1.f + __expf(-x0));
            g.y = v.y * __fdividef(x1, 1.f + __expf(-x1));
            g.z = v.z * __fdividef(x2, 1.f + __expf(-x2));
            g.w = v.w * __fdividef(x3, 1.f + __expf(-x3));
            *(float4*)&an_s[n * 132 + (t & 31) * 4] = g;
        }
        __syncthreads();

        // prefetch next pair while B/C/D run
        if (pl < PB - 1) {
            const float4* anp = (const float4*)(anb + (p + 1) * (Nn * Dd));
            #pragma unroll
            for (int j = 0; j < 4; j++) {
                int i4 = t + j * 256;
                pf[j] = anp[i4];
                pfd[j] = __ldg(&ldist[(p + 1) * Nn + (i4 >> 5)]);
            }
            pm = __ldg(&maskp[(p + 1) * Nn + lane]);
        }

        // ---- B: energy partials — warp w owns e-chunk [w*16,+16), lane = n
        {
            ull a2[8];
            #pragma unroll
            for (int i = 0; i < 4; i++) {
                double2 av = *(double2*)&an_s[lane * 132 + w * 16 + i * 4];
                a2[i * 2 + 0] = U64(av.x);
                a2[i * 2 + 1] = U64(av.y);
            }
            const float* qkp = &qk_s[pl * 8 * 128 + w * 16];
            #pragma unroll
            for (int h = 0; h < 8; h++) {
                ull acc2 = 0ULL;
                #pragma unroll
                for (int i = 0; i < 4; i++) {
                    double2 q2 = *(const double2*)&qkp[h * 128 + i * 4]; // bcast
                    acc2 = fma2(a2[i * 2 + 0], U64(q2.x), acc2);
                    acc2 = fma2(a2[i * 2 + 1], U64(q2.y), acc2);
                }
                float2 a = upk2(acc2);
                epart[(w * 8 + h) * 32 + lane] = a.x + a.y;
            }
        }
        __syncthreads();

        // ---- C: reduce + softmax over n (no max pass): warp w = head, lane = n
        {
            const int h = w, n = lane;
            float en = eb_s[pl * 8 + h];
            #pragma unroll
            for (int wc = 0; wc < 8; wc++) en += epart[(wc * 8 + h) * 32 + n];
            en += (1.f - pm_cur) * (-1e9f);
            float ex = __expf(en);
            float exm = ex * pm_cur;
            float s = ex, smm = exm;
            #pragma unroll
            for (int o = 16; o > 0; o >>= 1) {
                s   += __shfl_xor_sync(0xffffffffu, s, o);
                smm += __shfl_xor_sync(0xffffffffu, smm, o);
            }
            float rinv = __fdividef(1.f, s);
            float at = ex * rinv;
            if (attn_out) {
                int b = (int)(p >> 10), c = (int)(p & 1023);
                attn_out[((size_t)(b * Hh + h) * Cc + c) * Nn + n] = at;
            }
            attn_s[n * 12 + h] = at * pm_cur;
            if (n == 0) g_asum[p * Hh + h] = smm * rinv;
        }
        __syncthreads();

        // ---- D: wsum[h,e] = sum_n attnm[h,n]*an[n,e]; thread = (e, h-half)
        {
            const int e = t & 127, hh = t >> 7;
            ull acc01 = 0ULL, acc23 = 0ULL;
            #pragma unroll 8
            for (int n = 0; n < 32; n++) {
                float av = an_s[n * 132 + e];                      // conflict-free
                ull av2 = pk2(av, av);
                double2 at2 = *(double2*)&attn_s[n * 12 + hh * 4]; // bcast LDS.128
                acc01 = fma2(av2, U64(at2.x), acc01);
                acc23 = fma2(av2, U64(at2.y), acc23);
            }
            float2 a01 = upk2(acc01), a23 = upk2(acc23);
            float* wout = &g_wsum[(p * Hh + hh * 4) * Dd + e];
            wout[0] = a01.x; wout[128] = a01.y; wout[256] = a23.x; wout[384] = a23.y;
        }
        __syncthreads();
    }
}

// ---------------------------------------------------------------------------
// K3 v2: context[p, h*16+dd] = wsum[p,h,:] @ Wv[:, h*16+dd] + asum*bv + query
// 32 pairs per block, 1 CTA/SM; thread accumulates 4 pairs at fixed (h,dd0).
// smem = 50560 floats = 202240 B
// ---------------------------------------------------------------------------
__global__ __launch_bounds__(256, 1) void k_ctx(const float* __restrict__ Wv,
                                                const float* __restrict__ bv,
                                                float* __restrict__ ctx_out)
{
    extern __shared__ float sm[];
    float* Wv_s   = sm;                  // 128*128 = 16384
    float* ws_s   = sm + 16384;          // 256 rows (32p*8h) * 132 = 33792
    float* asum_s = sm + 50176;          // 256
    float* bv_s   = sm + 50432;          // 128

    const int t = threadIdx.x;
    const int p0 = blockIdx.x * 32;

    #pragma unroll
    for (int j = 0; j < 16; j++) {
        int i4 = t + j * 256;
        ((float4*)Wv_s)[i4] = ((const float4*)Wv)[i4];
    }
    #pragma unroll
    for (int j = 0; j < 32; j++) {
        int i4 = t + j * 256;                       // 8192 float4 = 32p*8h*32
        int row = i4 >> 5, e4 = i4 & 31;
        float4 v = ((const float4*)(g_wsum + (size_t)p0 * Hh * Dd))[i4];
        *(float4*)&ws_s[row * 132 + e4 * 4] = v;
    }
    asum_s[t] = g_asum[(size_t)p0 * Hh + t];        // 256 = 32p*8h
    if (t < 128) bv_s[t] = bv[t];
    __syncthreads();

    const int w = t >> 5, lane = t & 31;
    const int h = lane >> 2, dd0 = (lane & 3) * 4;
    const float* wvp = &Wv_s[h * 16 + dd0];
    ull a01[4] = {0ULL, 0ULL, 0ULL, 0ULL};
    ull a23[4] = {0ULL, 0ULL, 0ULL, 0ULL};

    #pragma unroll 8
    for (int e4 = 0; e4 < 32; e4++) {
        float skk[4][4];
        #pragma unroll
        for (int k = 0; k < 4; k++)
            *(float4*)skk[k] = *(float4*)&ws_s[((w + 8 * k) * 8 + h) * 132 + e4 * 4];
        #pragma unroll
        for (int j = 0; j < 4; j++) {
            double2 wv = *(const double2*)&wvp[(e4 * 4 + j) * 128];
            #pragma unroll
            for (int k = 0; k < 4; k++) {
                ull s2 = pk2(skk[k][j], skk[k][j]);
                a01[k] = fma2(s2, U64(wv.x), a01[k]);
                a23[k] = fma2(s2, U64(wv.y), a23[k]);
            }
        }
    }

    float4 b4 = *(const float4*)&bv_s[h * 16 + dd0];
    #pragma unroll
    for (int k = 0; k < 4; k++) {
        const int pl = w + 8 * k;
        float as = asum_s[pl * 8 + h];
        float4 q4 = *(const float4*)&g_query[(size_t)(p0 + pl) * Dd + h * 16 + dd0];
        float2 lo = upk2(a01[k]), hi = upk2(a23[k]);
        float4 r;
        r.x = lo.x + as * b4.x + q4.x;
        r.y = lo.y + as * b4.y + q4.y;
        r.z = hi.x + as * b4.z + q4.z;
        r.w = hi.y + as * b4.w + q4.w;
        *(float4*)&ctx_out[(size_t)(p0 + pl) * Dd + h * 16 + dd0] = r;
    }
}

// ---------------------------------------------------------------------------
extern "C" void kernel_launch(void* const* d_in, const int* in_sizes, int n_in,
                              void* d_out, int out_size)
{
    const float* aq    = (const float*)d_in[0];
    const float* anb   = (const float*)d_in[1];
    const float* ldist = (const float*)d_in[2];
    const float* maskp = (const float*)d_in[3];
    const float* Wq    = (const float*)d_in[4];
    const float* bq    = (const float*)d_in[5];
    const float* Wk    = (const float*)d_in[6];
    const float* bk    = (const float*)d_in[7];
    const float* Wv    = (const float*)d_in[8];
    const float* bv    = (const float*)d_in[9];
    const float* Wf    = (const float*)d_in[10];
    const float* bf    = (const float*)d_in[11];

    float* out = (float*)d_out;
    const size_t attn_elems = (size_t)NP * Hh * Nn;   // 4194304
    const size_t ctx_elems  = (size_t)NP * Dd;        // 2097152
    float* attn_out = nullptr;
    float* ctx_out  = nullptr;
    if ((size_t)out_size >= attn_elems + ctx_elems) { attn_out = out; ctx_out = out + attn_elems; }
    else if ((size_t)out_size == attn_elems)        { attn_out = out; }
    else                                            { ctx_out = out; }

    const int SM1 = (128 * 132 + 32 * 132 + 128) * 4;   // 84992
    const int SM2 = 10784 * 4;                          // 43136
    const int SM3 = 50560 * 4;                          // 202240

    cudaFuncSetAttribute(k_query, cudaFuncAttributeMaxDynamicSharedMemorySize, SM1);
    cudaFuncSetAttribute(k_main,  cudaFuncAttributeMaxDynamicSharedMemorySize, SM2);
    cudaFuncSetAttribute(k_ctx,   cudaFuncAttributeMaxDynamicSharedMemorySize, SM3);

    k_query<<<NP / 32, 256, SM1>>>(aq, Wq, bq);
    k_main<<<NP / PB, 256, SM2>>>(anb, ldist, maskp, Wk, bk, Wf, bf, attn_out);
    if (ctx_out)
        k_ctx<<<NP / 32, 256, SM3>>>(Wv, bv, ctx_out);
}

// round 13
// speedup vs baseline: 1.2322x; 1.0204x over previous
#include <cuda_runtime.h>
#include <cuda_bf16.h>
#include <cstdint>

// Problem constants
#define Bb   16
#define Cc   1024
#define Nn   32
#define Hh   8
#define Dd   128
#define NP   (Bb*Cc)          // 16384 (b,c) pairs
#define QSCALE 0.25f          // Dh^-0.5 = 16^-0.5
#define PB   4                // pairs per k_main block

// Scratch (device globals — no runtime allocation allowed)
__device__ float g_query[(size_t)NP * Dd];           // 8 MB
__device__ float g_wsum[(size_t)NP * Hh * Dd];       // 64 MB
__device__ float g_asum[(size_t)NP * Hh];            // 512 KB

// ---- packed fp32x2 helpers (Blackwell FFMA2) -------------------------------
typedef unsigned long long ull;
__device__ __forceinline__ ull fma2(ull a, ull b, ull c) {
    ull d; asm("fma.rn.f32x2 %0, %1, %2, %3;" : "=l"(d) : "l"(a), "l"(b), "l"(c));
    return d;
}
__device__ __forceinline__ ull pk2(float lo, float hi) {
    ull r; asm("mov.b64 %0, {%1, %2};" : "=l"(r) : "f"(lo), "f"(hi)); return r;
}
__device__ __forceinline__ float2 upk2(ull v) {
    float2 r; asm("mov.b64 {%0, %1}, %2;" : "=f"(r.x), "=f"(r.y) : "l"(v)); return r;
}
#define U64(d) __double_as_longlong(d)

// ---------------------------------------------------------------------------
// K1: query[p,d] = atom_query[p,:] @ Wq + bq      (32 pairs per block)
// ---------------------------------------------------------------------------
__global__ __launch_bounds__(256) void k_query(const float* __restrict__ aq,
                                               const float* __restrict__ Wq,
                                               const float* __restrict__ bq)
{
    extern __shared__ float sm[];
    float* Wq_s = sm;                  // 128*132
    float* aq_s = Wq_s + 128 * 132;    // 32*132
    float* bq_s = aq_s + 32 * 132;     // 128
    const int t = threadIdx.x;

    #pragma unroll
    for (int j = 0; j < 16; j++) {
        int i4 = t + j * 256;
        int f = i4 >> 5, d4 = i4 & 31;
        float4 v = ((const float4*)Wq)[i4];
        *(float4*)&Wq_s[f * 132 + d4 * 4] = v;
    }
    if (t < 128) bq_s[t] = bq[t];

    const int p0 = blockIdx.x * 32;
    #pragma unroll
    for (int j = 0; j < 4; j++) {
        int i4 = t + j * 256;
        int pl = i4 >> 5, e4 = i4 & 31;
        float4 v = ((const float4*)(aq + (size_t)p0 * Dd))[i4];
        *(float4*)&aq_s[pl * 132 + e4 * 4] = v;
    }
    __syncthreads();

    const int w = t >> 5, lane = t & 31;
    const int pl0 = w * 4, d0 = lane * 4;
    ull acc[4][2];
    #pragma unroll
    for (int k = 0; k < 4; k++) { acc[k][0] = 0ULL; acc[k][1] = 0ULL; }
    #pragma unroll 4
    for (int f = 0; f < 128; f++) {
        double2 wv = *(double2*)&Wq_s[f * 132 + d0];     // LDS.128
        #pragma unroll
        for (int k = 0; k < 4; k++) {
            float a = aq_s[(pl0 + k) * 132 + f];         // broadcast
            ull a2 = pk2(a, a);
            acc[k][0] = fma2(a2, U64(wv.x), acc[k][0]);
            acc[k][1] = fma2(a2, U64(wv.y), acc[k][1]);
        }
    }
    float4 b4 = *(float4*)&bq_s[d0];
    #pragma unroll
    for (int k = 0; k < 4; k++) {
        float2 lo = upk2(acc[k][0]), hi = upk2(acc[k][1]);
        float4 r = { lo.x + b4.x, lo.y + b4.y, hi.x + b4.z, hi.y + b4.w };
        *(float4*)&g_query[(size_t)(p0 + pl0 + k) * Dd + d0] = r;
    }
}

// ---------------------------------------------------------------------------
// K2 v4: 4 pairs per block, 4 CTAs/SM (32 warps). Wk in 4 quarter-stages,
// Wf/bf in registers. Per pair: R3's A/B/C/D phases unchanged.
// smem = 10784 floats = 43136 B
// ---------------------------------------------------------------------------
__global__ __launch_bounds__(256, 4) void k_main(const float* __restrict__ anb,
                                                 const float* __restrict__ ldist,
                                                 const float* __restrict__ maskp,
                                                 const float* __restrict__ Wk,
                                                 const float* __restrict__ bk,
                                                 const float* __restrict__ Wf,
                                                 const float* __restrict__ bf,
                                                 float* __restrict__ attn_out)
{
    extern __shared__ float sm[];
    // persistent
    float* qk_s = sm;                    // 4p*8h rows * 128 = 4096
    float* eb_s = sm + 4096;             // 32
    float* U    = sm + 4128;             // union (6656 floats)
    // phase 1 view
    float* Wst_s   = U;                  // 128e * 36 = 4608 (quarter stage)
    float* query_s = U + 4608;           // 4*132 = 528
    float* bk_s    = U + 5136;           // 128
    // phase 2 view
    float* an_s   = U;                   // 32*132 = 4224
    float* epart  = U + 4224;            // 8w*8h*32n = 2048
    float* attn_s = U + 6272;            // 32*12 = 384  [n*12 + h]

    const int t = threadIdx.x;
    const int p0 = blockIdx.x * PB;
    const int w = t >> 5, lane = t & 31;

    // per-thread gate params (thread only ever touches e = 4*(t&31)..+3)
    const float4 Wf4 = ((const float4*)Wf)[t & 31];
    const float4 bf4 = ((const float4*)bf)[t & 31];

    if (t < 128) bk_s[t] = bk[t];
    if (t < 128) {   // query for 4 pairs (512 floats = 128 float4), pitch 132
        int pl = t >> 5, e4 = t & 31;
        float4 v = ((const float4*)(g_query + (size_t)p0 * Dd))[t];
        *(float4*)&query_s[pl * 132 + e4 * 4] = v;
    }

    // ---- qk: 4 quarter-stages of Wk, each covers 2 heads (32 out-dims)
    const int e_col = t & 127, hl = t >> 7;
    #pragma unroll
    for (int s = 0; s < 4; s++) {
        __syncthreads();   // s=0: covers query/bk stores; s>0: Wst reuse
        #pragma unroll
        for (int j = 0; j < 4; j++) {
            int idx = t + j * 256;                  // 0..1023
            int e = idx >> 3, q = idx & 7;          // 8 float4 per e-row
            float4 v = ((const float4*)Wk)[e * 32 + s * 8 + q];
            *(float4*)&Wst_s[e * 36 + q * 4] = v;
        }
        __syncthreads();
        const int h = s * 2 + hl;
        ull wk2[8];
        #pragma unroll
        for (int i = 0; i < 4; i++) {
            double2 w2 = *(double2*)&Wst_s[e_col * 36 + hl * 16 + i * 4];
            wk2[i * 2 + 0] = U64(w2.x);
            wk2[i * 2 + 1] = U64(w2.y);
        }
        #pragma unroll
        for (int p = 0; p < PB; p++) {
            ull acc2 = 0ULL;
            #pragma unroll
            for (int i = 0; i < 4; i++) {
                double2 q2 = *(double2*)&query_s[p * 132 + h * 16 + i * 4]; // bcast
                acc2 = fma2(wk2[i * 2 + 0], U64(q2.x), acc2);
                acc2 = fma2(wk2[i * 2 + 1], U64(q2.y), acc2);
            }
            float2 a = upk2(acc2);
            qk_s[(p * 8 + h) * 128 + e_col] = (a.x + a.y) * QSCALE;
        }
    }
    __syncthreads();
    // energy bias eb[p,h] = scaled q . bk  (query_s/bk_s still valid)
    if (t < 8 * PB) {
        int p = t >> 3, h = t & 7;
        float acc = 0.f;
        #pragma unroll
        for (int dd = 0; dd < 16; dd++)
            acc += query_s[p * 132 + h * 16 + dd] * bk_s[h * 16 + dd];
        eb_s[t] = acc * QSCALE;
    }
    __syncthreads();

    // prefetch for pair 0
    float4 pf[4]; float pfd[4]; float pm;
    {
        const float4* anp = (const float4*)(anb + (size_t)p0 * (Nn * Dd));
        #pragma unroll
        for (int j = 0; j < 4; j++) {
            int i4 = t + j * 256;
            pf[j] = anp[i4];
            pfd[j] = __ldg(&ldist[(size_t)p0 * Nn + (i4 >> 5)]);
        }
        pm = __ldg(&maskp[(size_t)p0 * Nn + lane]);
    }

    for (int pl = 0; pl < PB; pl++) {
        const size_t p = (size_t)(p0 + pl);
        const float pm_cur = pm;

        // ---- A: gated an: an[n,e] = anb * swish(dist*Wf+bf)
        #pragma unroll
        for (int j = 0; j < 4; j++) {
            int n = (t + j * 256) >> 5;
            float4 v = pf[j];
            float dval = pfd[j];
            float x0 = fmaf(dval, Wf4.x, bf4.x);
            float x1 = fmaf(dval, Wf4.y, bf4.y);
            float x2 = fmaf(dval, Wf4.z, bf4.z);
            float x3 = fmaf(dval, Wf4.w, bf4.w);
            float4 g;
            g.x = v.x * __fdividef(x0, 1.f + __expf(-x0));
            g.y = v.y * __fdividef(x1, 1.f + __expf(-x1));
            g.z = v.z * __fdividef(x2, 1.f + __expf(-x2));
            g.w = v.w * __fdividef(x3, 1.f + __expf(-x3));
            *(float4*)&an_s[n * 132 + (t & 31) * 4] = g;
        }
        __syncthreads();

        // prefetch next pair while B/C/D run
        if (pl < PB - 1) {
            const float4* anp = (const float4*)(anb + (p + 1) * (Nn * Dd));
            #pragma unroll
            for (int j = 0; j < 4; j++) {
                int i4 = t + j * 256;
                pf[j] = anp[i4];
                pfd[j] = __ldg(&ldist[(p + 1) * Nn + (i4 >> 5)]);
            }
            pm = __ldg(&maskp[(p + 1) * Nn + lane]);
        }

        // ---- B: energy partials — warp w owns e-chunk [w*16,+16), lane = n
        {
            ull a2[8];
            #pragma unroll
            for (int i = 0; i < 4; i++) {
                double2 av = *(double2*)&an_s[lane * 132 + w * 16 + i * 4];
                a2[i * 2 + 0] = U64(av.x);
                a2[i * 2 + 1] = U64(av.y);
            }
            const float* qkp = &qk_s[pl * 8 * 128 + w * 16];
            #pragma unroll
            for (int h = 0; h < 8; h++) {
                ull acc2 = 0ULL;
                #pragma unroll
                for (int i = 0; i < 4; i++) {
                    double2 q2 = *(const double2*)&qkp[h * 128 + i * 4]; // bcast
                    acc2 = fma2(a2[i * 2 + 0], U64(q2.x), acc2);
                    acc2 = fma2(a2[i * 2 + 1], U64(q2.y), acc2);
                }
                float2 a = upk2(acc2);
                epart[(w * 8 + h) * 32 + lane] = a.x + a.y;
            }
        }
        __syncthreads();

        // ---- C: reduce + softmax over n (no max pass): warp w = head, lane = n
        {
            const int h = w, n = lane;
            float en = eb_s[pl * 8 + h];
            #pragma unroll
            for (int wc = 0; wc < 8; wc++) en += epart[(wc * 8 + h) * 32 + n];
            en += (1.f - pm_cur) * (-1e9f);
            float ex = __expf(en);
            float exm = ex * pm_cur;
            float s = ex, smm = exm;
            #pragma unroll
            for (int o = 16; o > 0; o >>= 1) {
                s   += __shfl_xor_sync(0xffffffffu, s, o);
                smm += __shfl_xor_sync(0xffffffffu, smm, o);
            }
            float rinv = __fdividef(1.f, s);
            float at = ex * rinv;
            if (attn_out) {
                int b = (int)(p >> 10), c = (int)(p & 1023);
                attn_out[((size_t)(b * Hh + h) * Cc + c) * Nn + n] = at;
            }
            attn_s[n * 12 + h] = at * pm_cur;
            if (n == 0) g_asum[p * Hh + h] = smm * rinv;
        }
        __syncthreads();

        // ---- D: wsum[h,e] = sum_n attnm[h,n]*an[n,e]; thread = (e, h-half)
        {
            const int e = t & 127, hh = t >> 7;
            ull acc01 = 0ULL, acc23 = 0ULL;
            #pragma unroll 8
            for (int n = 0; n < 32; n++) {
                float av = an_s[n * 132 + e];                      // conflict-free
                ull av2 = pk2(av, av);
                double2 at2 = *(double2*)&attn_s[n * 12 + hh * 4]; // bcast LDS.128
                acc01 = fma2(av2, U64(at2.x), acc01);
                acc23 = fma2(av2, U64(at2.y), acc23);
            }
            float2 a01 = upk2(acc01), a23 = upk2(acc23);
            float* wout = &g_wsum[(p * Hh + hh * 4) * Dd + e];
            wout[0] = a01.x; wout[128] = a01.y; wout[256] = a23.x; wout[384] = a23.y;
        }
        __syncthreads();
    }
}

// ---------------------------------------------------------------------------
// K3 v3 (fixed): context = wsum @ Wv + asum*bv + query
// 16 pairs per block, Wv via coalesced LDG.128 from L1 (no smem copy).
// Warp = one pair's full (h,dd) tile; handles pairs w and w+8.
// FIX vs R12: Wv row stride in double2 units is 32 (128 floats / 4), not 64.
// smem = 17152 floats = 68608 B -> 3 CTAs/SM (24 warps)
// ---------------------------------------------------------------------------
__global__ __launch_bounds__(256, 3) void k_ctx(const float* __restrict__ Wv,
                                                const float* __restrict__ bv,
                                                float* __restrict__ ctx_out)
{
    extern __shared__ float sm[];
    float* ws_s   = sm;                  // 128 rows (16p*8h) * 132 = 16896
    float* asum_s = sm + 16896;          // 128
    float* bv_s   = sm + 17024;          // 128

    const int t = threadIdx.x;
    const int p0 = blockIdx.x * 16;

    #pragma unroll
    for (int j = 0; j < 16; j++) {
        int i4 = t + j * 256;                       // 4096 float4 = 16p*8h*32
        int row = i4 >> 5, e4 = i4 & 31;
        float4 v = ((const float4*)(g_wsum + (size_t)p0 * Hh * Dd))[i4];
        *(float4*)&ws_s[row * 132 + e4 * 4] = v;
    }
    if (t < 128) { asum_s[t] = g_asum[(size_t)p0 * Hh + t]; bv_s[t] = bv[t]; }
    __syncthreads();

    const int w = t >> 5, lane = t & 31;
    const int h = lane >> 2, dd0 = (lane & 3) * 4;
    // Wv row-major [e][d]; thread reads Wv[e*128 + h*16 + dd0] as double2.
    // double2 = 4 floats -> row stride = 128/4 = 32 double2.
    const double2* wvp = (const double2*)&Wv[h * 16 + dd0];

    ull a01[2] = {0ULL, 0ULL};
    ull a23[2] = {0ULL, 0ULL};

    #pragma unroll 4
    for (int e4 = 0; e4 < 32; e4++) {
        float s0[4], s1[4];
        *(float4*)s0 = *(float4*)&ws_s[((w    ) * 8 + h) * 132 + e4 * 4]; // dedup LDS.128
        *(float4*)s1 = *(float4*)&ws_s[((w + 8) * 8 + h) * 132 + e4 * 4];
        #pragma unroll
        for (int j = 0; j < 4; j++) {
            double2 wv = __ldg(&wvp[(e4 * 4 + j) * 32]);       // coalesced LDG.128, L1-hot
            ull w01 = U64(wv.x), w23 = U64(wv.y);
            ull v0 = pk2(s0[j], s0[j]);
            ull v1 = pk2(s1[j], s1[j]);
            a01[0] = fma2(v0, w01, a01[0]);
            a23[0] = fma2(v0, w23, a23[0]);
            a01[1] = fma2(v1, w01, a01[1]);
            a23[1] = fma2(v1, w23, a23[1]);
        }
    }

    float4 b4 = *(const float4*)&bv_s[h * 16 + dd0];
    #pragma unroll
    for (int k = 0; k < 2; k++) {
        const int pl = w + 8 * k;
        float as = asum_s[pl * 8 + h];
        float4 q4 = *(const float4*)&g_query[(size_t)(p0 + pl) * Dd + h * 16 + dd0];
        float2 lo = upk2(a01[k]), hi = upk2(a23[k]);
        float4 r;
        r.x = lo.x + as * b4.x + q4.x;
        r.y = lo.y + as * b4.y + q4.y;
        r.z = hi.x + as * b4.z + q4.z;
        r.w = hi.y + as * b4.w + q4.w;
        *(float4*)&ctx_out[(size_t)(p0 + pl) * Dd + h * 16 + dd0] = r;
    }
}

// ---------------------------------------------------------------------------
extern "C" void kernel_launch(void* const* d_in, const int* in_sizes, int n_in,
                              void* d_out, int out_size)
{
    const float* aq    = (const float*)d_in[0];
    const float* anb   = (const float*)d_in[1];
    const float* ldist = (const float*)d_in[2];
    const float* maskp = (const float*)d_in[3];
    const float* Wq    = (const float*)d_in[4];
    const float* bq    = (const float*)d_in[5];
    const float* Wk    = (const float*)d_in[6];
    const float* bk    = (const float*)d_in[7];
    const float* Wv    = (const float*)d_in[8];
    const float* bv    = (const float*)d_in[9];
    const float* Wf    = (const float*)d_in[10];
    const float* bf    = (const float*)d_in[11];

    float* out = (float*)d_out;
    const size_t attn_elems = (size_t)NP * Hh * Nn;   // 4194304
    const size_t ctx_elems  = (size_t)NP * Dd;        // 2097152
    float* attn_out = nullptr;
    float* ctx_out  = nullptr;
    if ((size_t)out_size >= attn_elems + ctx_elems) { attn_out = out; ctx_out = out + attn_elems; }
    else if ((size_t)out_size == attn_elems)        { attn_out = out; }
    else                                            { ctx_out = out; }

    const int SM1 = (128 * 132 + 32 * 132 + 128) * 4;   // 84992
    const int SM2 = 10784 * 4;                          // 43136
    const int SM3 = 17152 * 4;                          // 68608

    cudaFuncSetAttribute(k_query, cudaFuncAttributeMaxDynamicSharedMemorySize, SM1);
    cudaFuncSetAttribute(k_main,  cudaFuncAttributeMaxDynamicSharedMemorySize, SM2);
    cudaFuncSetAttribute(k_ctx,   cudaFuncAttributeMaxDynamicSharedMemorySize, SM3);

    k_query<<<NP / 32, 256, SM1>>>(aq, Wq, bq);
    k_main<<<NP / PB, 256, SM2>>>(anb, ldist, maskp, Wk, bk, Wf, bf, attn_out);
    if (ctx_out)
        k_ctx<<<NP / 16, 256, SM3>>>(Wv, bv, ctx_out);
}